// round 13
// baseline (speedup 1.0000x reference)
#include <cuda_runtime.h>
#include <cuda_fp16.h>
#include <cuda_bf16.h>
#include <cstdint>

#define N_MAX 100000
#define E_MAX 1600000
#define D 128
#define SCAN_B 1024
#define NB_MAX ((N_MAX + SCAN_B - 1) / SCAN_B)   // 98

// Scratch (allocation-free rule: __device__ globals)
__device__ int    g_deg[N_MAX];
__device__ int    g_off[N_MAX + 1];
__device__ int    g_cur[N_MAX];
__device__ int    g_src[E_MAX];
__device__ float  g_dinv[N_MAX];
__device__ int    g_bsum[NB_MAX];
__device__ int    g_bbase[NB_MAX];
__device__ __half g_yh[(size_t)N_MAX * D];    // 25.6 MB, L2-resident
__device__ __half g_Wth[D * D];               // W^T hi  (Wt[n][k]), 32KB
__device__ __half g_Wtl[D * D];               // W^T lo residual, 32KB

// ---------------------------------------------------------------- deg zero
__global__ void k_zero_deg(int n) {
    int i = blockIdx.x * blockDim.x + threadIdx.x;
    if (i < n) g_deg[i] = 0;
}

// ---------------------------------------------------------------- deg count
__global__ void k_count(const int* __restrict__ col, int E) {
    int e = blockIdx.x * blockDim.x + threadIdx.x;
    if (e < E) atomicAdd(&g_deg[col[e]], 1);
}

// ---------------------------------------------------------------- pass 1: per-block sums of deg
__global__ void k_blocksum(int n) {
    __shared__ int warps[32];
    int tid = threadIdx.x, lane = tid & 31, w = tid >> 5;
    int i = blockIdx.x * SCAN_B + tid;
    int v = (i < n) ? g_deg[i] : 0;
    #pragma unroll
    for (int s = 16; s > 0; s >>= 1) v += __shfl_down_sync(0xffffffffu, v, s);
    if (lane == 0) warps[w] = v;
    __syncthreads();
    if (w == 0) {
        int x = warps[lane];
        #pragma unroll
        for (int s = 16; s > 0; s >>= 1) x += __shfl_down_sync(0xffffffffu, x, s);
        if (lane == 0) g_bsum[blockIdx.x] = x;
    }
}

// ---------------------------------------------------------------- pass 2: scan the <=128 block sums (1 block)
__global__ void k_scan_bsums(int nb, int n) {
    __shared__ int warps[4];
    int tid = threadIdx.x, lane = tid & 31, w = tid >> 5;
    int v = (tid < nb) ? g_bsum[tid] : 0;
    int inc = v;
    #pragma unroll
    for (int s = 1; s < 32; s <<= 1) {
        int t = __shfl_up_sync(0xffffffffu, inc, s);
        if (lane >= s) inc += t;
    }
    if (lane == 31) warps[w] = inc;
    __syncthreads();
    int wbase = 0;
    #pragma unroll
    for (int j = 0; j < 4; j++) if (j < w) wbase += warps[j];
    inc += wbase;
    if (tid < nb) g_bbase[tid] = inc - v;      // exclusive base per block
    if (tid == nb - 1) g_off[n] = inc;         // total edge count
}

// ---------------------------------------------------------------- pass 3: local scan + scatter offsets (+dinv fused)
__global__ void k_scatter_off(int n) {
    __shared__ int warps[32];
    int tid = threadIdx.x, lane = tid & 31, w = tid >> 5;
    int i = blockIdx.x * SCAN_B + tid;
    int v = (i < n) ? g_deg[i] : 0;
    int inc = v;
    #pragma unroll
    for (int s = 1; s < 32; s <<= 1) {
        int t = __shfl_up_sync(0xffffffffu, inc, s);
        if (lane >= s) inc += t;
    }
    if (lane == 31) warps[w] = inc;
    __syncthreads();
    if (w == 0) {
        int x = warps[lane];
        #pragma unroll
        for (int st = 1; st < 32; st <<= 1) {
            int t = __shfl_up_sync(0xffffffffu, x, st);
            if (lane >= st) x += t;
        }
        warps[lane] = x;
    }
    __syncthreads();
    int wbase = (w > 0) ? warps[w - 1] : 0;
    int ex = g_bbase[blockIdx.x] + inc + wbase - v;   // exclusive prefix
    if (i < n) {
        g_off[i]  = ex;
        g_cur[i]  = ex;
        g_dinv[i] = rsqrtf((float)(v + 1));           // +1 self-loop
    }
}

// ---------------------------------------------------------------- bucket fill (CSR by destination)
__global__ void k_fill(const int* __restrict__ row, const int* __restrict__ col, int E) {
    int e = blockIdx.x * blockDim.x + threadIdx.x;
    if (e < E) {
        int c = col[e];
        int pos = atomicAdd(&g_cur[c], 1);
        g_src[pos] = row[e];
    }
}

// ---------------------------------------------------------------- W split + transpose: Wt[n][k] = hi/lo(W[k][n])
__global__ void k_prepw(const float* __restrict__ W) {
    int i = blockIdx.x * blockDim.x + threadIdx.x;   // 16384 threads
    int k = i >> 7, nn = i & 127;
    float w = W[k * D + nn];
    __half hi = __float2half_rn(w);
    __half lo = __float2half_rn(w - __half2float(hi));
    g_Wth[nn * D + k] = hi;
    g_Wtl[nn * D + k] = lo;
}

// ---------------------------------------------------------------- split-fp16 tensor-core GEMM
// y = half((x @ W) * dinv[row]); 64 rows/block, 4 warps, 16 rows/warp.
#define XS_STRIDE 136   // halves; bank = (4g+tg)%32, conflict-free fragments
__global__ void __launch_bounds__(128) k_gemm_mma(const float* __restrict__ x, int n) {
    __shared__ __half xs_hi[64 * XS_STRIDE];
    __shared__ __half xs_lo[64 * XS_STRIDE];

    int tid = threadIdx.x;
    int r0 = blockIdx.x * 64;

    // Load 64x128 fp32 tile, split into hi/lo fp16 in smem
    for (int idx = tid; idx < 64 * 32; idx += 128) {   // 32 float4 per row
        int r = idx >> 5, c4 = (idx & 31) << 2;
        int node = r0 + r;
        float4 v = (node < n) ? *reinterpret_cast<const float4*>(x + (size_t)node * D + c4)
                              : make_float4(0.f, 0.f, 0.f, 0.f);
        __half h0 = __float2half_rn(v.x), h1 = __float2half_rn(v.y);
        __half h2 = __float2half_rn(v.z), h3 = __float2half_rn(v.w);
        __half l0 = __float2half_rn(v.x - __half2float(h0));
        __half l1 = __float2half_rn(v.y - __half2float(h1));
        __half l2 = __float2half_rn(v.z - __half2float(h2));
        __half l3 = __float2half_rn(v.w - __half2float(h3));
        __half* ph = &xs_hi[r * XS_STRIDE + c4];
        __half* pl = &xs_lo[r * XS_STRIDE + c4];
        ph[0] = h0; ph[1] = h1; ph[2] = h2; ph[3] = h3;
        pl[0] = l0; pl[1] = l1; pl[2] = l2; pl[3] = l3;
    }
    __syncthreads();

    int w    = tid >> 5;          // warp id: rows [w*16, w*16+16)
    int lane = tid & 31;
    int g    = lane >> 2;         // 0..7
    int tg   = lane & 3;          // 0..3
    int mw   = w * 16;

    float acc[16][4];
    #pragma unroll
    for (int j = 0; j < 16; j++) {
        acc[j][0] = 0.f; acc[j][1] = 0.f; acc[j][2] = 0.f; acc[j][3] = 0.f;
    }

    const __half* rowh0 = &xs_hi[(mw + g) * XS_STRIDE];
    const __half* rowh8 = &xs_hi[(mw + g + 8) * XS_STRIDE];
    const __half* rowl0 = &xs_lo[(mw + g) * XS_STRIDE];
    const __half* rowl8 = &xs_lo[(mw + g + 8) * XS_STRIDE];

    for (int k0 = 0; k0 < D; k0 += 16) {
        int ka = k0 + tg * 2;
        uint32_t ah0 = *reinterpret_cast<const uint32_t*>(rowh0 + ka);
        uint32_t ah1 = *reinterpret_cast<const uint32_t*>(rowh8 + ka);
        uint32_t ah2 = *reinterpret_cast<const uint32_t*>(rowh0 + ka + 8);
        uint32_t ah3 = *reinterpret_cast<const uint32_t*>(rowh8 + ka + 8);
        uint32_t al0 = *reinterpret_cast<const uint32_t*>(rowl0 + ka);
        uint32_t al1 = *reinterpret_cast<const uint32_t*>(rowl8 + ka);
        uint32_t al2 = *reinterpret_cast<const uint32_t*>(rowl0 + ka + 8);
        uint32_t al3 = *reinterpret_cast<const uint32_t*>(rowl8 + ka + 8);

        #pragma unroll
        for (int j = 0; j < 16; j++) {
            int nrow = (j * 8 + g) * D + ka;   // Wt[n][k], k pairs contiguous
            uint32_t bh0 = *reinterpret_cast<const uint32_t*>(&g_Wth[nrow]);
            uint32_t bh1 = *reinterpret_cast<const uint32_t*>(&g_Wth[nrow + 8]);
            uint32_t bl0 = *reinterpret_cast<const uint32_t*>(&g_Wtl[nrow]);
            uint32_t bl1 = *reinterpret_cast<const uint32_t*>(&g_Wtl[nrow + 8]);

            asm volatile(
                "mma.sync.aligned.m16n8k16.row.col.f32.f16.f16.f32 "
                "{%0,%1,%2,%3}, {%4,%5,%6,%7}, {%8,%9}, {%0,%1,%2,%3};"
                : "+f"(acc[j][0]), "+f"(acc[j][1]), "+f"(acc[j][2]), "+f"(acc[j][3])
                : "r"(ah0), "r"(ah1), "r"(ah2), "r"(ah3), "r"(bh0), "r"(bh1));
            asm volatile(
                "mma.sync.aligned.m16n8k16.row.col.f32.f16.f16.f32 "
                "{%0,%1,%2,%3}, {%4,%5,%6,%7}, {%8,%9}, {%0,%1,%2,%3};"
                : "+f"(acc[j][0]), "+f"(acc[j][1]), "+f"(acc[j][2]), "+f"(acc[j][3])
                : "r"(ah0), "r"(ah1), "r"(ah2), "r"(ah3), "r"(bl0), "r"(bl1));
            asm volatile(
                "mma.sync.aligned.m16n8k16.row.col.f32.f16.f16.f32 "
                "{%0,%1,%2,%3}, {%4,%5,%6,%7}, {%8,%9}, {%0,%1,%2,%3};"
                : "+f"(acc[j][0]), "+f"(acc[j][1]), "+f"(acc[j][2]), "+f"(acc[j][3])
                : "r"(al0), "r"(al1), "r"(al2), "r"(al3), "r"(bh0), "r"(bh1));
        }
    }

    // Epilogue: *dinv, convert to half, store (C frag: c0,c1=(g,tg*2..+1), c2,c3=(g+8,..))
    int rg0 = r0 + mw + g;
    int rg8 = rg0 + 8;
    float d0 = (rg0 < n) ? g_dinv[rg0] : 0.f;
    float d8 = (rg8 < n) ? g_dinv[rg8] : 0.f;
    #pragma unroll
    for (int j = 0; j < 16; j++) {
        int c = j * 8 + tg * 2;
        if (rg0 < n) {
            __half2 h = __floats2half2_rn(acc[j][0] * d0, acc[j][1] * d0);
            *reinterpret_cast<__half2*>(&g_yh[(size_t)rg0 * D + c]) = h;
        }
        if (rg8 < n) {
            __half2 h = __floats2half2_rn(acc[j][2] * d8, acc[j][3] * d8);
            *reinterpret_cast<__half2*>(&g_yh[(size_t)rg8 * D + c]) = h;
        }
    }
}

// ---------------------------------------------------------------- pull aggregation + epilogue
// One WARP per node; lane owns 4 dims (uint2 = 4 halves). fp32 accumulate.
__global__ void k_agg(const float* __restrict__ b, float* __restrict__ out, int n) {
    int gw = (blockIdx.x * blockDim.x + threadIdx.x) >> 5;
    if (gw >= n) return;
    int lane = threadIdx.x & 31;

    const __half* yself = g_yh + (size_t)gw * D + lane * 4;
    uint2 u = *reinterpret_cast<const uint2*>(yself);
    float2 f0 = __half22float2(*reinterpret_cast<__half2*>(&u.x));
    float2 f1 = __half22float2(*reinterpret_cast<__half2*>(&u.y));
    float a0 = f0.x, a1 = f0.y, a2 = f1.x, a3 = f1.y;   // self-loop term

    int s = g_off[gw];
    int e = g_off[gw + 1];
    #pragma unroll 2
    for (int i = s; i < e; i++) {
        int src = g_src[i];                              // warp-broadcast load
        uint2 v = *reinterpret_cast<const uint2*>(g_yh + (size_t)src * D + lane * 4);
        float2 g0 = __half22float2(*reinterpret_cast<__half2*>(&v.x));
        float2 g1 = __half22float2(*reinterpret_cast<__half2*>(&v.y));
        a0 += g0.x; a1 += g0.y; a2 += g1.x; a3 += g1.y;
    }

    float di = g_dinv[gw];
    float4 bb = *reinterpret_cast<const float4*>(b + lane * 4);
    float4 o;
    o.x = fmaxf(fmaf(a0, di, bb.x), 0.f);
    o.y = fmaxf(fmaf(a1, di, bb.y), 0.f);
    o.z = fmaxf(fmaf(a2, di, bb.z), 0.f);
    o.w = fmaxf(fmaf(a3, di, bb.w), 0.f);
    *reinterpret_cast<float4*>(out + (size_t)gw * D + lane * 4) = o;
}

// ----------------------------------------------------------------
extern "C" void kernel_launch(void* const* d_in, const int* in_sizes, int n_in,
                              void* d_out, int out_size) {
    const float* x  = (const float*)d_in[0];
    const int*   ei = (const int*)  d_in[1];
    const float* W  = (const float*)d_in[2];
    const float* b  = (const float*)d_in[3];
    float*       out = (float*)d_out;

    int n = in_sizes[0] / D;
    int E = in_sizes[1] / 2;
    const int* row = ei;
    const int* col = ei + E;
    int nb = (n + SCAN_B - 1) / SCAN_B;

    k_zero_deg   <<<(n + 255) / 256, 256>>>(n);
    k_count      <<<(E + 255) / 256, 256>>>(col, E);
    k_blocksum   <<<nb, SCAN_B>>>(n);
    k_scan_bsums <<<1, 128>>>(nb, n);
    k_scatter_off<<<nb, SCAN_B>>>(n);
    k_fill       <<<(E + 255) / 256, 256>>>(row, col, E);
    k_prepw      <<<(D * D) / 128, 128>>>(W);
    k_gemm_mma   <<<(n + 63) / 64, 128>>>(x, n);
    k_agg        <<<(n * 32 + 255) / 256, 256>>>(b, out, n);
}

// round 15
// speedup vs baseline: 1.4726x; 1.4726x over previous
#include <cuda_runtime.h>
#include <cuda_fp16.h>
#include <cuda_bf16.h>
#include <cstdint>

#define N_MAX 100000
#define E_MAX 1600000
#define D 128
#define SCAN_B 1024
#define NB_MAX ((N_MAX + SCAN_B - 1) / SCAN_B)   // 98

// Scratch (allocation-free rule: __device__ globals)
__device__ int    g_deg[N_MAX];
__device__ int    g_off[N_MAX + 1];
__device__ int    g_cur[N_MAX];
__device__ int    g_src[E_MAX];
__device__ float  g_dinv[N_MAX];
__device__ int    g_bsum[NB_MAX];
__device__ int    g_bbase[NB_MAX];
__device__ __half g_yh[(size_t)N_MAX * D];    // 25.6 MB, L2-resident
// W in MMA-fragment order: [ks(8)][j(16)][lane(32)] -> {bh0,bh1,bl0,bl1}, 64KB
__device__ uint4  g_Wpk[8 * 16 * 32];

// ---------------------------------------------------------------- deg zero
__global__ void k_zero_deg(int n) {
    int i = blockIdx.x * blockDim.x + threadIdx.x;
    if (i < n) g_deg[i] = 0;
}

// ---------------------------------------------------------------- deg count
__global__ void k_count(const int* __restrict__ col, int E) {
    int e = blockIdx.x * blockDim.x + threadIdx.x;
    if (e < E) atomicAdd(&g_deg[col[e]], 1);
}

// ---------------------------------------------------------------- pass 1: per-block sums of deg
__global__ void k_blocksum(int n) {
    __shared__ int warps[32];
    int tid = threadIdx.x, lane = tid & 31, w = tid >> 5;
    int i = blockIdx.x * SCAN_B + tid;
    int v = (i < n) ? g_deg[i] : 0;
    #pragma unroll
    for (int s = 16; s > 0; s >>= 1) v += __shfl_down_sync(0xffffffffu, v, s);
    if (lane == 0) warps[w] = v;
    __syncthreads();
    if (w == 0) {
        int x = warps[lane];
        #pragma unroll
        for (int s = 16; s > 0; s >>= 1) x += __shfl_down_sync(0xffffffffu, x, s);
        if (lane == 0) g_bsum[blockIdx.x] = x;
    }
}

// ---------------------------------------------------------------- pass 2: scan the <=128 block sums (1 block)
__global__ void k_scan_bsums(int nb, int n) {
    __shared__ int warps[4];
    int tid = threadIdx.x, lane = tid & 31, w = tid >> 5;
    int v = (tid < nb) ? g_bsum[tid] : 0;
    int inc = v;
    #pragma unroll
    for (int s = 1; s < 32; s <<= 1) {
        int t = __shfl_up_sync(0xffffffffu, inc, s);
        if (lane >= s) inc += t;
    }
    if (lane == 31) warps[w] = inc;
    __syncthreads();
    int wbase = 0;
    #pragma unroll
    for (int j = 0; j < 4; j++) if (j < w) wbase += warps[j];
    inc += wbase;
    if (tid < nb) g_bbase[tid] = inc - v;      // exclusive base per block
    if (tid == nb - 1) g_off[n] = inc;         // total edge count
}

// ---------------------------------------------------------------- pass 3: local scan + scatter offsets (+dinv fused)
__global__ void k_scatter_off(int n) {
    __shared__ int warps[32];
    int tid = threadIdx.x, lane = tid & 31, w = tid >> 5;
    int i = blockIdx.x * SCAN_B + tid;
    int v = (i < n) ? g_deg[i] : 0;
    int inc = v;
    #pragma unroll
    for (int s = 1; s < 32; s <<= 1) {
        int t = __shfl_up_sync(0xffffffffu, inc, s);
        if (lane >= s) inc += t;
    }
    if (lane == 31) warps[w] = inc;
    __syncthreads();
    if (w == 0) {
        int x = warps[lane];
        #pragma unroll
        for (int st = 1; st < 32; st <<= 1) {
            int t = __shfl_up_sync(0xffffffffu, x, st);
            if (lane >= st) x += t;
        }
        warps[lane] = x;
    }
    __syncthreads();
    int wbase = (w > 0) ? warps[w - 1] : 0;
    int ex = g_bbase[blockIdx.x] + inc + wbase - v;   // exclusive prefix
    if (i < n) {
        g_off[i]  = ex;
        g_cur[i]  = ex;
        g_dinv[i] = rsqrtf((float)(v + 1));           // +1 self-loop
    }
}

// ---------------------------------------------------------------- bucket fill (CSR by destination)
__global__ void k_fill(const int* __restrict__ row, const int* __restrict__ col, int E) {
    int e = blockIdx.x * blockDim.x + threadIdx.x;
    if (e < E) {
        int c = col[e];
        int pos = atomicAdd(&g_cur[c], 1);
        g_src[pos] = row[e];
    }
}

// ---------------------------------------------------------------- W split into fragment-packed layout
// For (ks, j, lane): g = lane>>2, tg = lane&3, n = j*8+g, ka = ks*16 + tg*2
// bh0 = half2{hi(W[ka][n]),   hi(W[ka+1][n])}
// bh1 = half2{hi(W[ka+8][n]), hi(W[ka+9][n])}
// bl0/bl1 = fp16 residuals at same positions.
__global__ void k_prepw(const float* __restrict__ W) {
    int i = blockIdx.x * blockDim.x + threadIdx.x;   // 4096 threads
    int lane = i & 31, j = (i >> 5) & 15, ks = i >> 9;
    int g = lane >> 2, tg = lane & 3;
    int nn = j * 8 + g;
    int ka = ks * 16 + tg * 2;

    float w0 = W[(ka + 0) * D + nn];
    float w1 = W[(ka + 1) * D + nn];
    float w2 = W[(ka + 8) * D + nn];
    float w3 = W[(ka + 9) * D + nn];

    __half h0 = __float2half_rn(w0), h1 = __float2half_rn(w1);
    __half h2 = __float2half_rn(w2), h3 = __float2half_rn(w3);
    __half l0 = __float2half_rn(w0 - __half2float(h0));
    __half l1 = __float2half_rn(w1 - __half2float(h1));
    __half l2 = __float2half_rn(w2 - __half2float(h2));
    __half l3 = __float2half_rn(w3 - __half2float(h3));

    __half2 ph0 = __halves2half2(h0, h1);
    __half2 ph1 = __halves2half2(h2, h3);
    __half2 pl0 = __halves2half2(l0, l1);
    __half2 pl1 = __halves2half2(l2, l3);

    uint4 v;
    v.x = *reinterpret_cast<uint32_t*>(&ph0);
    v.y = *reinterpret_cast<uint32_t*>(&ph1);
    v.z = *reinterpret_cast<uint32_t*>(&pl0);
    v.w = *reinterpret_cast<uint32_t*>(&pl1);
    g_Wpk[i] = v;
}

// ---------------------------------------------------------------- split-fp16 tensor-core GEMM
// y = half((x @ W) * dinv[row]); 64 rows/block, 4 warps, 16 rows/warp.
#define XS_STRIDE 136   // halves; conflict-free fragments
__global__ void __launch_bounds__(128) k_gemm_mma(const float* __restrict__ x, int n) {
    __shared__ __half xs_hi[64 * XS_STRIDE];
    __shared__ __half xs_lo[64 * XS_STRIDE];

    int tid = threadIdx.x;
    int r0 = blockIdx.x * 64;

    // Load 64x128 fp32 tile, split into hi/lo fp16 in smem
    for (int idx = tid; idx < 64 * 32; idx += 128) {   // 32 float4 per row
        int r = idx >> 5, c4 = (idx & 31) << 2;
        int node = r0 + r;
        float4 v = (node < n) ? *reinterpret_cast<const float4*>(x + (size_t)node * D + c4)
                              : make_float4(0.f, 0.f, 0.f, 0.f);
        __half h0 = __float2half_rn(v.x), h1 = __float2half_rn(v.y);
        __half h2 = __float2half_rn(v.z), h3 = __float2half_rn(v.w);
        __half l0 = __float2half_rn(v.x - __half2float(h0));
        __half l1 = __float2half_rn(v.y - __half2float(h1));
        __half l2 = __float2half_rn(v.z - __half2float(h2));
        __half l3 = __float2half_rn(v.w - __half2float(h3));
        __half* ph = &xs_hi[r * XS_STRIDE + c4];
        __half* pl = &xs_lo[r * XS_STRIDE + c4];
        ph[0] = h0; ph[1] = h1; ph[2] = h2; ph[3] = h3;
        pl[0] = l0; pl[1] = l1; pl[2] = l2; pl[3] = l3;
    }
    __syncthreads();

    int w    = tid >> 5;          // warp id: rows [w*16, w*16+16)
    int lane = tid & 31;
    int g    = lane >> 2;         // 0..7
    int tg   = lane & 3;          // 0..3
    int mw   = w * 16;

    float acc[16][4];
    #pragma unroll
    for (int j = 0; j < 16; j++) {
        acc[j][0] = 0.f; acc[j][1] = 0.f; acc[j][2] = 0.f; acc[j][3] = 0.f;
    }

    const __half* rowh0 = &xs_hi[(mw + g) * XS_STRIDE];
    const __half* rowh8 = &xs_hi[(mw + g + 8) * XS_STRIDE];
    const __half* rowl0 = &xs_lo[(mw + g) * XS_STRIDE];
    const __half* rowl8 = &xs_lo[(mw + g + 8) * XS_STRIDE];

    #pragma unroll
    for (int ks = 0; ks < 8; ks++) {
        int ka = ks * 16 + tg * 2;
        uint32_t ah0 = *reinterpret_cast<const uint32_t*>(rowh0 + ka);
        uint32_t ah1 = *reinterpret_cast<const uint32_t*>(rowh8 + ka);
        uint32_t ah2 = *reinterpret_cast<const uint32_t*>(rowh0 + ka + 8);
        uint32_t ah3 = *reinterpret_cast<const uint32_t*>(rowh8 + ka + 8);
        uint32_t al0 = *reinterpret_cast<const uint32_t*>(rowl0 + ka);
        uint32_t al1 = *reinterpret_cast<const uint32_t*>(rowl8 + ka);
        uint32_t al2 = *reinterpret_cast<const uint32_t*>(rowl0 + ka + 8);
        uint32_t al3 = *reinterpret_cast<const uint32_t*>(rowl8 + ka + 8);

        const uint4* wrow = &g_Wpk[(ks * 16) * 32 + lane];

        #pragma unroll
        for (int j = 0; j < 16; j++) {
            uint4 wv = wrow[j * 32];   // one LDG.128: {bh0, bh1, bl0, bl1}

            asm volatile(
                "mma.sync.aligned.m16n8k16.row.col.f32.f16.f16.f32 "
                "{%0,%1,%2,%3}, {%4,%5,%6,%7}, {%8,%9}, {%0,%1,%2,%3};"
                : "+f"(acc[j][0]), "+f"(acc[j][1]), "+f"(acc[j][2]), "+f"(acc[j][3])
                : "r"(ah0), "r"(ah1), "r"(ah2), "r"(ah3), "r"(wv.x), "r"(wv.y));
            asm volatile(
                "mma.sync.aligned.m16n8k16.row.col.f32.f16.f16.f32 "
                "{%0,%1,%2,%3}, {%4,%5,%6,%7}, {%8,%9}, {%0,%1,%2,%3};"
                : "+f"(acc[j][0]), "+f"(acc[j][1]), "+f"(acc[j][2]), "+f"(acc[j][3])
                : "r"(ah0), "r"(ah1), "r"(ah2), "r"(ah3), "r"(wv.z), "r"(wv.w));
            asm volatile(
                "mma.sync.aligned.m16n8k16.row.col.f32.f16.f16.f32 "
                "{%0,%1,%2,%3}, {%4,%5,%6,%7}, {%8,%9}, {%0,%1,%2,%3};"
                : "+f"(acc[j][0]), "+f"(acc[j][1]), "+f"(acc[j][2]), "+f"(acc[j][3])
                : "r"(al0), "r"(al1), "r"(al2), "r"(al3), "r"(wv.x), "r"(wv.y));
        }
    }

    // Epilogue: *dinv, convert to half, store (C frag: c0,c1=(g,tg*2..+1), c2,c3=(g+8,..))
    int rg0 = r0 + mw + g;
    int rg8 = rg0 + 8;
    float d0 = (rg0 < n) ? g_dinv[rg0] : 0.f;
    float d8 = (rg8 < n) ? g_dinv[rg8] : 0.f;
    #pragma unroll
    for (int j = 0; j < 16; j++) {
        int c = j * 8 + tg * 2;
        if (rg0 < n) {
            __half2 h = __floats2half2_rn(acc[j][0] * d0, acc[j][1] * d0);
            *reinterpret_cast<__half2*>(&g_yh[(size_t)rg0 * D + c]) = h;
        }
        if (rg8 < n) {
            __half2 h = __floats2half2_rn(acc[j][2] * d8, acc[j][3] * d8);
            *reinterpret_cast<__half2*>(&g_yh[(size_t)rg8 * D + c]) = h;
        }
    }
}

// ---------------------------------------------------------------- pull aggregation + epilogue
// One WARP per node; lane owns 4 dims (uint2 = 4 halves). fp32 accumulate.
__global__ void k_agg(const float* __restrict__ b, float* __restrict__ out, int n) {
    int gw = (blockIdx.x * blockDim.x + threadIdx.x) >> 5;
    if (gw >= n) return;
    int lane = threadIdx.x & 31;

    const __half* yself = g_yh + (size_t)gw * D + lane * 4;
    uint2 u = *reinterpret_cast<const uint2*>(yself);
    float2 f0 = __half22float2(*reinterpret_cast<__half2*>(&u.x));
    float2 f1 = __half22float2(*reinterpret_cast<__half2*>(&u.y));
    float a0 = f0.x, a1 = f0.y, a2 = f1.x, a3 = f1.y;   // self-loop term

    int s = g_off[gw];
    int e = g_off[gw + 1];
    #pragma unroll 2
    for (int i = s; i < e; i++) {
        int src = g_src[i];                              // warp-broadcast load
        uint2 v = *reinterpret_cast<const uint2*>(g_yh + (size_t)src * D + lane * 4);
        float2 g0 = __half22float2(*reinterpret_cast<__half2*>(&v.x));
        float2 g1 = __half22float2(*reinterpret_cast<__half2*>(&v.y));
        a0 += g0.x; a1 += g0.y; a2 += g1.x; a3 += g1.y;
    }

    float di = g_dinv[gw];
    float4 bb = *reinterpret_cast<const float4*>(b + lane * 4);
    float4 o;
    o.x = fmaxf(fmaf(a0, di, bb.x), 0.f);
    o.y = fmaxf(fmaf(a1, di, bb.y), 0.f);
    o.z = fmaxf(fmaf(a2, di, bb.z), 0.f);
    o.w = fmaxf(fmaf(a3, di, bb.w), 0.f);
    *reinterpret_cast<float4*>(out + (size_t)gw * D + lane * 4) = o;
}

// ----------------------------------------------------------------
extern "C" void kernel_launch(void* const* d_in, const int* in_sizes, int n_in,
                              void* d_out, int out_size) {
    const float* x  = (const float*)d_in[0];
    const int*   ei = (const int*)  d_in[1];
    const float* W  = (const float*)d_in[2];
    const float* b  = (const float*)d_in[3];
    float*       out = (float*)d_out;

    int n = in_sizes[0] / D;
    int E = in_sizes[1] / 2;
    const int* row = ei;
    const int* col = ei + E;
    int nb = (n + SCAN_B - 1) / SCAN_B;

    k_zero_deg   <<<(n + 255) / 256, 256>>>(n);
    k_count      <<<(E + 255) / 256, 256>>>(col, E);
    k_blocksum   <<<nb, SCAN_B>>>(n);
    k_scan_bsums <<<1, 128>>>(nb, n);
    k_scatter_off<<<nb, SCAN_B>>>(n);
    k_fill       <<<(E + 255) / 256, 256>>>(row, col, E);
    k_prepw      <<<32, 128>>>(W);
    k_gemm_mma   <<<(n + 63) / 64, 128>>>(x, n);
    k_agg        <<<(n * 32 + 255) / 256, 256>>>(b, out, n);
}